// round 9
// baseline (speedup 1.0000x reference)
#include <cuda_runtime.h>

// ---------------- problem constants ----------------
#define B_     64
#define BH     32            // batch elements per CTA (b-half)
#define CIN    32
#define COUT   16
#define HH     64
#define WW     64
#define S_     4096          // 64*64 output locations
#define KK     288           // CIN * 3 * 3

#define SLICES 16            // k-split factor
#define KSL    (KK / SLICES) // 18 k-steps per slice

// smem: patch [KK][BH] (128B rows, XOR-swizzled) + weight [KK][COUT] (64B rows, XOR-swizzled)
#define SP_BYTES (KK * BH * 4)               // 36864
#define SW_BYTES (KK * COUT * 4)             // 18432
#define SMEM_BYTES (SP_BYTES + SW_BYTES)     // 55296  -> 4 CTAs/SM

// Scratch: X transposed to [ih][iw][cin][b]  (33.55 MB) — static device global.
__device__ float g_Xt[(size_t)HH * WW * CIN * B_];

// ---------------- tiny f32x2 helpers ----------------
__device__ __forceinline__ void fma2(unsigned long long& d,
                                     unsigned long long a, unsigned long long b) {
    asm("fma.rn.f32x2 %0, %1, %2, %0;" : "+l"(d) : "l"(a), "l"(b));
}
__device__ __forceinline__ unsigned long long splat2(float x) {
    unsigned long long r;
    asm("mov.b64 %0, {%1, %1};" : "=l"(r) : "f"(x));
    return r;
}
__device__ __forceinline__ unsigned long long add2(unsigned long long a,
                                                   unsigned long long b) {
    unsigned long long r;
    asm("add.rn.f32x2 %0, %1, %2;" : "=l"(r) : "l"(a), "l"(b));
    return r;
}

// ---------------------------------------------------------------------------
// Pre-pass: X[b][cin][ih][iw] -> Xt[ih][iw][cin][b]  (coalesced both sides)
// ---------------------------------------------------------------------------
__global__ void __launch_bounds__(256) transpose_kernel(const float* __restrict__ X) {
    __shared__ float tile[64][65];
    const int cin = blockIdx.x >> 6;
    const int ih  = blockIdx.x & 63;
    const int t   = threadIdx.x;
    {
        const int iw = t & 63;
        const int bg = t >> 6;
        const float* src = X + (size_t)cin * (HH * WW) + (size_t)ih * WW;
        #pragma unroll
        for (int r = 0; r < 16; ++r) {
            const int b = bg * 16 + r;
            tile[iw][b] = src[(size_t)b * (CIN * HH * WW) + iw];
        }
    }
    __syncthreads();
    {
        const int b  = t & 63;
        const int wg = t >> 6;
        float* dst = g_Xt + ((size_t)ih * WW) * (CIN * B_) + (size_t)cin * B_;
        #pragma unroll
        for (int r = 0; r < 16; ++r) {
            const int iw = wg * 16 + r;
            dst[(size_t)iw * (CIN * B_) + b] = tile[iw][b];
        }
    }
}

// ---------------------------------------------------------------------------
// Main kernel: one CTA per (location s, b-half). 256 threads =
//   16 k-slices x (4 bg x 4 cg); thread tile = 8b x 4c via packed f32x2.
// Patch rows (128B): 32B chunk bg stored at slot bg ^ (k&3)  -> the two
//   slices inside a warp (rows 18 apart, 18 mod 4 == 2) read opposite 64B
//   halves: conflict-free LDS.128.
// Weight rows (64B): row k at byte (k*64) ^ (((k>>1)&1)<<6) (bit1 of 18 set
//   -> warp's slice pair lands in opposite halves), 16B piece cg at chunk
//   (cg>>1)^(k&1).
// ---------------------------------------------------------------------------
__global__ void __launch_bounds__(256, 4) lc_kernel(const float* __restrict__ Wt,
                                                    const float* __restrict__ bias,
                                                    float* __restrict__ out) {
    extern __shared__ float sm[];
    float4* sp4 = (float4*)sm;                       // patch: KK*8 float4
    float4* sw4 = (float4*)(sm + KK * BH);           // weight: KK*4 float4

    const int bid  = blockIdx.x;
    const int s    = bid >> 1;
    const int half = bid & 1;
    const int oh   = s >> 6;
    const int ow   = s & 63;
    const int tid  = threadIdx.x;
    const float bs = bias[s];

    // ---- stage per-location weight: 1152 float4, swizzled rows ----
    {
        const float4* gw = (const float4*)(Wt + (size_t)s * (KK * COUT));
        #pragma unroll
        for (int t = tid; t < (KK * COUT) / 4; t += 256) {
            const int k = t >> 2;
            const int q = t & 3;
            const int base4 = (k * 4) ^ (((k >> 1) & 1) << 2);        // row-pair XOR
            const int idx4  = base4 + (((q >> 1) ^ (k & 1)) << 1) + (q & 1);
            sw4[idx4] = gw[t];
        }
    }

    // ---- stage patch: 9 taps x (32 cin x 8 float4) = exactly 1 float4/thread/tap.
    //      bias pre-added; OOB taps become exactly bias (matches unfold+bias). ----
    {
        const int cin = tid >> 3;       // 0..31
        const int q   = tid & 7;        // float4 within the 32-float b-half row
        #pragma unroll
        for (int ij = 0; ij < 9; ++ij) {
            const int ih = oh + ij / 3 - 1;
            const int iw = ow + ij % 3 - 1;
            const bool valid = ((unsigned)ih < (unsigned)HH) && ((unsigned)iw < (unsigned)WW);
            float4 v = make_float4(0.f, 0.f, 0.f, 0.f);
            if (valid) {
                const float4* src = (const float4*)(g_Xt + (size_t)(ih * WW + iw) * (CIN * B_));
                v = src[cin * 16 + half * 8 + q];
            }
            v.x += bs; v.y += bs; v.z += bs; v.w += bs;
            const int k = cin * 9 + ij;
            sp4[k * 8 + (((q >> 1) ^ (k & 3)) << 1) + (q & 1)] = v;
        }
    }
    __syncthreads();

    // ---- mainloop: 18 k-steps, 8b x 4c per thread ----
    const int slice = tid >> 4;          // 0..15
    const int idx   = tid & 15;
    const int bg    = idx >> 2;          // 0..3 -> b base = bg*8 (within half)
    const int cg    = idx & 3;           // 0..3 -> c base = cg*4
    const int kbase = slice * KSL;

    const char* spc = (const char*)sm;
    const char* swc = (const char*)sm + SP_BYTES;

    unsigned long long acc[4][4];
    #pragma unroll
    for (int i = 0; i < 4; ++i)
        #pragma unroll
        for (int j = 0; j < 4; ++j) acc[i][j] = 0ull;

    #pragma unroll 6
    for (int k = 0; k < KSL; ++k) {
        const int r = kbase + k;
        const int poff = r * 128 + ((bg ^ (r & 3)) << 5);
        const ulonglong2 u0 = *(const ulonglong2*)(spc + poff);
        const ulonglong2 u1 = *(const ulonglong2*)(spc + poff + 16);
        const int woff = ((r * 64) ^ (((r >> 1) & 1) << 6))
                       + (((cg >> 1) ^ (r & 1)) << 5) + ((cg & 1) << 4);
        const float4 w = *(const float4*)(swc + woff);

        const unsigned long long p[4]  = { u0.x, u0.y, u1.x, u1.y };
        const unsigned long long w2[4] = { splat2(w.x), splat2(w.y),
                                           splat2(w.z), splat2(w.w) };
        #pragma unroll
        for (int i = 0; i < 4; ++i)
            #pragma unroll
            for (int j = 0; j < 4; ++j)
                fma2(acc[i][j], p[i], w2[j]);
    }

    // ---- k-slice reduction through smem (reuses patch region) ----
    __syncthreads();
    unsigned long long* part = (unsigned long long*)sm;   // part[E][17], E = c*16 + bpair
    #pragma unroll
    for (int ii = 0; ii < 4; ++ii) {
        const int i = (ii + bg) & 3;       // bank rotation
        #pragma unroll
        for (int jj = 0; jj < 4; ++jj) {
            const int j = (jj + cg) & 3;
            const int E = (cg * 4 + j) * 16 + bg * 4 + i;
            part[E * 17 + slice] = acc[i][j];
        }
    }
    __syncthreads();

    // 256 (c,bpair) entries, one per thread: sum 16 slices, write out[b][c][s]
    {
        const int E  = tid;
        const int c  = E >> 4;
        const int bp = E & 15;
        const unsigned long long* base = part + E * 17;
        unsigned long long sum = base[0];
        #pragma unroll
        for (int t = 1; t < SLICES; ++t) sum = add2(sum, base[t]);
        float lo, hi;
        asm("mov.b64 {%0, %1}, %2;" : "=f"(lo), "=f"(hi) : "l"(sum));
        const int b0 = half * BH + 2 * bp;
        out[((size_t)b0       * COUT + c) * S_ + s] = lo;
        out[((size_t)(b0 + 1) * COUT + c) * S_ + s] = hi;
    }
}

// ---------------------------------------------------------------------------
extern "C" void kernel_launch(void* const* d_in, const int* in_sizes, int n_in,
                              void* d_out, int out_size) {
    const float* X  = nullptr;   // 8388608
    const float* Wt = nullptr;   // 18874368
    const float* Bp = nullptr;   // 4096
    for (int i = 0; i < n_in; ++i) {
        if      (in_sizes[i] == B_ * CIN * HH * WW) X  = (const float*)d_in[i];
        else if (in_sizes[i] == S_ * KK * COUT)     Wt = (const float*)d_in[i];
        else if (in_sizes[i] == S_)                 Bp = (const float*)d_in[i];
    }

    cudaFuncSetAttribute(lc_kernel, cudaFuncAttributeMaxDynamicSharedMemorySize, SMEM_BYTES);

    transpose_kernel<<<CIN * HH, 256>>>(X);
    lc_kernel<<<S_ * 2, 256, SMEM_BYTES>>>(Wt, Bp, (float*)d_out);
}

// round 10
// speedup vs baseline: 1.6034x; 1.6034x over previous
#include <cuda_runtime.h>

// ---------------- problem constants ----------------
#define B_     64
#define BH     32            // batch elements per CTA (b-half)
#define CIN    32
#define COUT   16
#define HH     64
#define WW     64
#define S_     4096
#define KK     288           // CIN * 3 * 3

#define SLICES 16
#define KSL    (KK / SLICES) // 18, k stride 16: r = slice + 16*k

// smem: patch [KK][32f] 128B rows (chunk-XOR swizzle) + weight stripes
#define SP_BYTES (KK * BH * 4)             // 36864
#define SW_BYTES (KK * COUT * 4)           // 18432 (144 stripes x 128B)
#define SMEM_BYTES (SP_BYTES + SW_BYTES)   // 55296 -> 4 CTAs/SM

// reduction scratch (reuses patch region): 64 rows x 34 u64 (272B rows)
#define PART_ROW_U64 34

// ---------------- device scratch (static, no alloc) ----------------
__device__ float g_Xt[(size_t)HH * WW * CIN * B_];          // 33.55 MB
__device__ float g_tmp[(size_t)S_ * 2 * 512];               // 16.78 MB

// ---------------- f32x2 helpers ----------------
__device__ __forceinline__ void fma2(unsigned long long& d,
                                     unsigned long long a, unsigned long long b) {
    asm("fma.rn.f32x2 %0, %1, %2, %0;" : "+l"(d) : "l"(a), "l"(b));
}
__device__ __forceinline__ unsigned long long splat2(float x) {
    unsigned long long r;
    asm("mov.b64 %0, {%1, %1};" : "=l"(r) : "f"(x));
    return r;
}
__device__ __forceinline__ unsigned long long add2(unsigned long long a,
                                                   unsigned long long b) {
    unsigned long long r;
    asm("add.rn.f32x2 %0, %1, %2;" : "=l"(r) : "l"(a), "l"(b));
    return r;
}

// ---------------------------------------------------------------------------
// Pre-pass: X[b][cin][ih][iw] -> Xt[ih][iw][cin][b]  (coalesced both sides)
// ---------------------------------------------------------------------------
__global__ void __launch_bounds__(256) transpose_kernel(const float* __restrict__ X) {
    __shared__ float tile[64][65];
    const int cin = blockIdx.x >> 6;
    const int ih  = blockIdx.x & 63;
    const int t   = threadIdx.x;
    {
        const int iw = t & 63;
        const int bg = t >> 6;
        const float* src = X + (size_t)cin * (HH * WW) + (size_t)ih * WW;
        #pragma unroll
        for (int r = 0; r < 16; ++r) {
            const int b = bg * 16 + r;
            tile[iw][b] = src[(size_t)b * (CIN * HH * WW) + iw];
        }
    }
    __syncthreads();
    {
        const int b  = t & 63;
        const int wg = t >> 6;
        float* dst = g_Xt + ((size_t)ih * WW) * (CIN * B_) + (size_t)cin * B_;
        #pragma unroll
        for (int r = 0; r < 16; ++r) {
            const int iw = wg * 16 + r;
            dst[(size_t)iw * (CIN * B_) + b] = tile[iw][b];
        }
    }
}

// ---------------------------------------------------------------------------
// Main kernel: 128 threads, one CTA per (s, b-half).
// Thread map: slice = tid>>3 (0..15), idx = tid&7, bg = idx>>1 (8b), cg = idx&1 (8c).
// Thread k-sequence: r = slice + 16*k, k = 0..17  (warp = 4 consecutive slices
//   -> rows distinct mod 4 every step; all swizzles hit the 4-phase floor,
//   and r&3 / r>>2 are per-thread constants -> linear addressing).
// Patch rows 128B, 32B chunk bg at slot bg ^ (r&3).
// Weight stripes: row r quarter q (16B) lives at stripe ((r>>2)*2 + (q&1)),
//   slot ((r&3)*2 + (q>>1))  -> warp's lo/hi loads each hit one stripe clean.
// Epilogue: shfl(16) pair-reduce, smem 8-way sum, contiguous float4 to g_tmp.
// ---------------------------------------------------------------------------
__global__ void __launch_bounds__(128, 4) lc_kernel(const float* __restrict__ Wt,
                                                    const float* __restrict__ bias,
                                                    float* __restrict__ unused) {
    extern __shared__ float sm[];
    float4* sp4 = (float4*)sm;                               // patch, KK*8 float4
    float4* sw4 = (float4*)((char*)sm + SP_BYTES);           // weight stripes

    const int bid  = blockIdx.x;
    const int s    = bid >> 1;
    const int half = bid & 1;
    const int oh   = s >> 6;
    const int ow   = s & 63;
    const int tid  = threadIdx.x;
    const float bs = bias[s];

    // ---- stage weight: 1152 float4 into stripe layout; one stripe per
    //      8-lane cluster (conflict-free STS.128), coalesced LDG ----
    {
        const float4* gw = (const float4*)(Wt + (size_t)s * (KK * COUT));
        #pragma unroll
        for (int i = tid; i < (KK * COUT) / 4; i += 128) {
            const int stripe = i >> 3;
            const int slot   = i & 7;
            const int k      = (stripe >> 1) * 4 + (slot >> 1);
            const int q      = ((slot & 1) << 1) + (stripe & 1);
            sw4[stripe * 8 + slot] = gw[k * 4 + q];
        }
    }

    // ---- stage patch: 9 taps x 256 float4; bias pre-added, OOB = bias ----
    #pragma unroll
    for (int ij = 0; ij < 9; ++ij) {
        const int ih = oh + ij / 3 - 1;
        const int iw = ow + ij % 3 - 1;
        const bool valid = ((unsigned)ih < (unsigned)HH) && ((unsigned)iw < (unsigned)WW);
        const float4* src = (const float4*)(g_Xt + (size_t)(valid ? (ih * WW + iw) : 0) * (CIN * B_));
        #pragma unroll
        for (int t = tid; t < (CIN * BH) / 4; t += 128) {    // 256 float4
            const int cin = t >> 3;
            const int q   = t & 7;
            float4 v = valid ? src[cin * 16 + half * 8 + q]
                             : make_float4(0.f, 0.f, 0.f, 0.f);
            v.x += bs; v.y += bs; v.z += bs; v.w += bs;
            const int r = cin * 9 + ij;
            sp4[r * 8 + (((q >> 1) ^ (r & 3)) << 1) + (q & 1)] = v;
        }
    }
    __syncthreads();

    // ---- mainloop: 18 strided k-steps, 8b x 8c per thread ----
    const int slice = tid >> 3;
    const int idx   = tid & 7;
    const int bg    = idx >> 1;
    const int cg    = idx & 1;
    const int s3    = slice & 3;

    const char* pbase = (const char*)sm + slice * 128 + ((bg ^ s3) << 5);
    const char* wbase = (const char*)sm + SP_BYTES
                      + ((slice >> 2) << 8) + (((s3 << 1) + cg) << 4);

    unsigned long long acc[4][8];
    #pragma unroll
    for (int i = 0; i < 4; ++i)
        #pragma unroll
        for (int j = 0; j < 8; ++j) acc[i][j] = 0ull;

    #pragma unroll 6
    for (int k = 0; k < KSL; ++k) {
        const ulonglong2 u0 = *(const ulonglong2*)(pbase + k * 2048);
        const ulonglong2 u1 = *(const ulonglong2*)(pbase + k * 2048 + 16);
        const float4 wlo = *(const float4*)(wbase + k * 1024);
        const float4 whi = *(const float4*)(wbase + k * 1024 + 128);

        const unsigned long long p[4] = { u0.x, u0.y, u1.x, u1.y };
        const unsigned long long w2[8] = {
            splat2(wlo.x), splat2(wlo.y), splat2(wlo.z), splat2(wlo.w),
            splat2(whi.x), splat2(whi.y), splat2(whi.z), splat2(whi.w)
        };
        #pragma unroll
        for (int i = 0; i < 4; ++i)
            #pragma unroll
            for (int j = 0; j < 8; ++j)
                fma2(acc[i][j], p[i], w2[j]);
    }

    // ---- reduce 16 slices: shfl pair (dist 16) -> 8 partials via smem ----
    #pragma unroll
    for (int i = 0; i < 4; ++i)
        #pragma unroll
        for (int j = 0; j < 8; ++j) {
            unsigned long long o = __shfl_down_sync(0xffffffffu, acc[i][j], 16);
            acc[i][j] = add2(acc[i][j], o);
        }

    __syncthreads();   // done reading patch smem
    unsigned long long* part = (unsigned long long*)sm;      // [64][34] u64
    const int lane = tid & 31;
    const int wrp  = tid >> 5;
    if (lane < 16) {
        ulonglong2* pr = (ulonglong2*)(part + (size_t)(wrp * 16 + lane) * PART_ROW_U64);
        #pragma unroll
        for (int i = 0; i < 4; ++i)
            #pragma unroll
            for (int j = 0; j < 8; j += 2) {
                ulonglong2 v; v.x = acc[i][j]; v.y = acc[i][j + 1];
                pr[(i * 8 + j) >> 1] = v;
            }
    }
    __syncthreads();

    // ---- final 8-way sum; thread t -> E = 2t, 2t+1; contiguous store ----
    {
        float res[4];
        #pragma unroll
        for (int e = 0; e < 2; ++e) {
            const int E  = tid * 2 + e;
            const int bp = E & 15;
            const int c  = E >> 4;
            const int ix = ((bp >> 2) << 1) + (c >> 3);      // bg*2+cg
            const int a  = ((bp & 3) << 3) + (c & 7);        // i*8+j
            unsigned long long sum = part[(size_t)ix * PART_ROW_U64 + a];
            #pragma unroll
            for (int m = 1; m < 8; ++m)
                sum = add2(sum, part[(size_t)(ix + 8 * m) * PART_ROW_U64 + a]);
            asm("mov.b64 {%0, %1}, %2;" : "=f"(res[2 * e]), "=f"(res[2 * e + 1]) : "l"(sum));
        }
        float4* o = (float4*)(g_tmp + (size_t)bid * 512 + tid * 4);
        *o = make_float4(res[0], res[1], res[2], res[3]);
    }
}

// ---------------------------------------------------------------------------
// Epilogue: g_tmp[(s*2+half)*512 + (c*16+bp)*2 + b0] -> out[(b*16+c)*S + s]
// CTA = 16 s-values x all 1024 (b,c) rows through a 66KB smem tile.
// Lane pairs write adjacent 32B halves -> 32B-granular global stores.
// ---------------------------------------------------------------------------
#define EP_PITCH 516
#define EP_SMEM  (32 * EP_PITCH * 4)   // 66048

__global__ void __launch_bounds__(256) epi_kernel(float* __restrict__ out) {
    extern __shared__ float es[];
    const int tid = threadIdx.x;
    const int s0  = blockIdx.x * 16;

    // load 32 tmp rows (bid = s*2+h) x 512 floats, coalesced
    const float4* src = (const float4*)(g_tmp + (size_t)(s0 * 2) * 512);
    #pragma unroll
    for (int t = tid; t < 32 * 128; t += 256) {
        const int row = t >> 7;
        ((float4*)(es + (size_t)row * EP_PITCH))[t & 127] = src[t];
    }
    __syncthreads();

    const int p  = tid >> 1;      // 0..127: (b,c)-row group
    const int hs = tid & 1;       // s half (8 values)
    #pragma unroll
    for (int rr = 0; rr < 8; ++rr) {
        const int R  = p + 128 * rr;          // 0..1023 = b*16 + c
        const int b  = R >> 4;
        const int c  = R & 15;
        const int h  = b >> 5;
        const int bp = (b >> 1) & 15;
        const int b0 = b & 1;
        const int col = ((c << 4) + bp) * 2 + b0;
        float v[8];
        #pragma unroll
        for (int z = 0; z < 8; ++z) {
            const int sl = hs * 8 + z;
            v[z] = es[(size_t)(sl * 2 + h) * EP_PITCH + col];
        }
        float4* o = (float4*)(out + (size_t)R * S_ + s0 + hs * 8);
        o[0] = make_float4(v[0], v[1], v[2], v[3]);
        o[1] = make_float4(v[4], v[5], v[6], v[7]);
    }
}

// ---------------------------------------------------------------------------
extern "C" void kernel_launch(void* const* d_in, const int* in_sizes, int n_in,
                              void* d_out, int out_size) {
    const float* X  = nullptr;   // 8388608
    const float* Wt = nullptr;   // 18874368
    const float* Bp = nullptr;   // 4096
    for (int i = 0; i < n_in; ++i) {
        if      (in_sizes[i] == B_ * CIN * HH * WW) X  = (const float*)d_in[i];
        else if (in_sizes[i] == S_ * KK * COUT)     Wt = (const float*)d_in[i];
        else if (in_sizes[i] == S_)                 Bp = (const float*)d_in[i];
    }

    cudaFuncSetAttribute(lc_kernel,  cudaFuncAttributeMaxDynamicSharedMemorySize, SMEM_BYTES);
    cudaFuncSetAttribute(epi_kernel, cudaFuncAttributeMaxDynamicSharedMemorySize, EP_SMEM);

    transpose_kernel<<<CIN * HH, 256>>>(X);
    lc_kernel<<<S_ * 2, 128, SMEM_BYTES>>>(Wt, Bp, (float*)d_out);
    epi_kernel<<<S_ / 16, 256, EP_SMEM>>>((float*)d_out);
}